// round 17
// baseline (speedup 1.0000x reference)
#include <cuda_runtime.h>
#include <cuda_bf16.h>
#include <cstdint>

#define BATCH   2
#define L_SEQ   4096
#define DMODEL  1024
#define NSTATE  64
#define M_ROWS  (BATCH * L_SEQ)   // 8192
#define SCHUNK  128
#define NCHUNK  (L_SEQ / SCHUNK)  // 32

// ---------------- scratch (allocation-free __device__ globals) ----------------
__device__ __align__(256) float g_ut [(size_t)M_ROWS * DMODEL];  // [b,D,L] fp32 (u)
__device__ __align__(256) float g_dA [DMODEL * NSTATE];
__device__ __align__(256) float g_cdb[DMODEL * NSTATE];
__device__ __align__(256) float g_e    [(size_t)BATCH * DMODEL * NCHUNK * NSTATE];
__device__ __align__(256) float g_carry[(size_t)BATCH * DMODEL * NCHUNK * NSTATE];
// pre-split bf16 operands
__device__ __align__(256) __nv_bfloat16 g_xh[(size_t)M_ROWS * DMODEL];
__device__ __align__(256) __nv_bfloat16 g_xl[(size_t)M_ROWS * DMODEL];
__device__ __align__(256) __nv_bfloat16 g_yh[(size_t)M_ROWS * DMODEL];  // [b,L,D]
__device__ __align__(256) __nv_bfloat16 g_yl[(size_t)M_ROWS * DMODEL];  // [b,L,D]
__device__ __align__(256) __nv_bfloat16 g_winh[DMODEL * DMODEL];
__device__ __align__(256) __nv_bfloat16 g_winl[DMODEL * DMODEL];
__device__ __align__(256) __nv_bfloat16 g_wouth[DMODEL * DMODEL];
__device__ __align__(256) __nv_bfloat16 g_woutl[DMODEL * DMODEL];

// ---------------- PTX helpers (sm_80-compatible) ----------------
__device__ __forceinline__ uint32_t smem_u32(const void* p) {
    uint32_t a;
    asm("{ .reg .u64 t; cvta.to.shared.u64 t, %1; cvt.u32.u64 %0, t; }" : "=r"(a) : "l"(p));
    return a;
}
__device__ __forceinline__ void ldsm_x4(uint32_t& r0, uint32_t& r1, uint32_t& r2, uint32_t& r3,
                                        uint32_t addr) {
    asm volatile("ldmatrix.sync.aligned.m8n8.x4.shared.b16 {%0,%1,%2,%3}, [%4];"
        : "=r"(r0), "=r"(r1), "=r"(r2), "=r"(r3) : "r"(addr));
}
__device__ __forceinline__ void mma_bf16(float* d, const uint32_t* a, const uint32_t* b) {
    asm volatile("mma.sync.aligned.m16n8k16.row.col.f32.bf16.bf16.f32 "
        "{%0,%1,%2,%3}, {%4,%5,%6,%7}, {%8,%9}, {%0,%1,%2,%3};"
        : "+f"(d[0]), "+f"(d[1]), "+f"(d[2]), "+f"(d[3])
        : "r"(a[0]), "r"(a[1]), "r"(a[2]), "r"(a[3]), "r"(b[0]), "r"(b[1]));
}
__device__ __forceinline__ void cp_async16(uint32_t s, const void* g) {
    asm volatile("cp.async.cg.shared.global [%0], [%1], 16;"
        :: "r"(s), "l"(__cvta_generic_to_global(g)) : "memory");
}
#define CP_COMMIT() asm volatile("cp.async.commit_group;" ::: "memory")
#define CP_WAIT1()  asm volatile("cp.async.wait_group 1;" ::: "memory")

__device__ __forceinline__ void split2(float v, __nv_bfloat16& h, __nv_bfloat16& l) {
    h = __float2bfloat16(v);
    l = __float2bfloat16(v - __bfloat162float(h));
}
__device__ __forceinline__ void split_store4(const float* __restrict__ src,
                                             __nv_bfloat16* __restrict__ hi,
                                             __nv_bfloat16* __restrict__ lo, int i) {
    float4 v = *(const float4*)(src + (size_t)i * 4);
    __nv_bfloat16 h0, h1, h2, h3, l0, l1, l2, l3;
    split2(v.x, h0, l0); split2(v.y, h1, l1);
    split2(v.z, h2, l2); split2(v.w, h3, l3);
    __nv_bfloat162 hp0 = __halves2bfloat162(h0, h1), hp1 = __halves2bfloat162(h2, h3);
    __nv_bfloat162 lp0 = __halves2bfloat162(l0, l1), lp1 = __halves2bfloat162(l2, l3);
    *(uint2*)(hi + (size_t)i * 4) = make_uint2(*(uint32_t*)&hp0, *(uint32_t*)&hp1);
    *(uint2*)(lo + (size_t)i * 4) = make_uint2(*(uint32_t*)&lp0, *(uint32_t*)&lp1);
}

// ---------------- merged prep + splits (one launch) ----------------
#define XQ  (M_ROWS * DMODEL / 4)    // 2097152
#define WQ  (DMODEL * DMODEL / 4)    // 262144
#define PQ  (DMODEL * NSTATE / 4)    // 16384
#define PREP_TOTAL (XQ + 2 * WQ + PQ)

__global__ void __launch_bounds__(256) prep_split(
    const float* __restrict__ x, const float* __restrict__ Win,
    const float* __restrict__ Wout, const float* __restrict__ A_log,
    const float* __restrict__ Bm, const float* __restrict__ Cm,
    const float* __restrict__ dt) {
    int i = blockIdx.x * 256 + threadIdx.x;
    if (i < XQ) {
        split_store4(x, g_xh, g_xl, i);
    } else if (i < XQ + WQ) {
        split_store4(Win, g_winh, g_winl, i - XQ);
    } else if (i < XQ + 2 * WQ) {
        split_store4(Wout, g_wouth, g_woutl, i - XQ - WQ);
    } else if (i < PREP_TOTAL) {
        int q = i - XQ - 2 * WQ;                // quad index into [DMODEL*NSTATE/4]
        int base = q * 4;
        int d = base >> 6;                      // same d for all 4 (64 | 4)
        float dtv = dt[d];
        float4 av = *(const float4*)(A_log + base);
        float4 bv = *(const float4*)(Bm + base);
        float4 cv = *(const float4*)(Cm + base);
        float4 dA, cdb;
        dA.x = expf(-expf(-av.x) * dtv); cdb.x = cv.x * bv.x * dtv;
        dA.y = expf(-expf(-av.y) * dtv); cdb.y = cv.y * bv.y * dtv;
        dA.z = expf(-expf(-av.z) * dtv); cdb.z = cv.z * bv.z * dtv;
        dA.w = expf(-expf(-av.w) * dtv); cdb.w = cv.w * bv.w * dtv;
        *(float4*)(g_dA + base)  = dA;
        *(float4*)(g_cdb + base) = cdb;
    }
}

// ---------------- HMMA bf16-split GEMM ----------------
// out = Ahl @ Whl^T + bias; M=8192, N=K=1024. CTA 128x128, BK=32.
// 256 threads = 8 warps, each 64(M) x 32(N). XOR-swizzled dense 64B rows.
// 3-stage ring, ONE __syncthreads per chunk, 2 CTAs/SM.
// EPI_T=false: write out[l][d] row-major ([b,L,D]).
// EPI_T=true : staged transpose -> g_ut [b,D,L] + fused scan phase-1 (chunk end
//              states into g_e) on the idle FMA pipe.
#define BUF_B    (128 * 64)                  // 8192 B per buffer (dense)
#define STAGE_B  (4 * BUF_B)                 // Ahi, Alo, Bhi, Blo = 32768 B
#define NSTAGE   3
#define GSMEM_B  (NSTAGE * STAGE_B)          // 98304 B -> 2 CTAs/SM

#define SWZ(r, c) ((uint32_t)((r) * 64 + (((c) ^ (((r) >> 1) & 3)) << 4)))

template<bool EPI_T>
__global__ void __launch_bounds__(256, 2)
gemm_hmma(const __nv_bfloat16* __restrict__ Ah, const __nv_bfloat16* __restrict__ Al,
          const __nv_bfloat16* __restrict__ Bh, const __nv_bfloat16* __restrict__ Bl,
          const float* __restrict__ bias, float* __restrict__ out) {
    extern __shared__ char smem[];
    const uint32_t sbase = smem_u32(smem);

    const int tid  = threadIdx.x;
    const int wid  = tid >> 5;
    const int lane = tid & 31;
    const int wm   = wid >> 2;                 // 0..1 -> 64-row block
    const int wn   = wid & 3;                  // 0..3 -> 32-col block
    const int bm   = blockIdx.y * 128;
    const int bn   = blockIdx.x * 128;

    // cp.async mapping: buffer = 128 rows x 4 x 16B chunks = 512 chunks; 256 thr -> 2 each
    const int r0c = tid >> 2, c0c = tid & 3;
    const int r1c = (tid + 256) >> 2, c1c = tid & 3;
    const __nv_bfloat16* gA0h = Ah + (size_t)(bm + r0c) * DMODEL + c0c * 8;
    const __nv_bfloat16* gA0l = Al + (size_t)(bm + r0c) * DMODEL + c0c * 8;
    const __nv_bfloat16* gB0h = Bh + (size_t)(bn + r0c) * DMODEL + c0c * 8;
    const __nv_bfloat16* gB0l = Bl + (size_t)(bn + r0c) * DMODEL + c0c * 8;
    const __nv_bfloat16* gA1h = Ah + (size_t)(bm + r1c) * DMODEL + c1c * 8;
    const __nv_bfloat16* gA1l = Al + (size_t)(bm + r1c) * DMODEL + c1c * 8;
    const __nv_bfloat16* gB1h = Bh + (size_t)(bn + r1c) * DMODEL + c1c * 8;
    const __nv_bfloat16* gB1l = Bl + (size_t)(bn + r1c) * DMODEL + c1c * 8;
    const uint32_t s0 = SWZ(r0c, c0c);
    const uint32_t s1 = SWZ(r1c, c1c);

    float acc[4][4][4];
#pragma unroll
    for (int mt = 0; mt < 4; mt++)
#pragma unroll
        for (int nt = 0; nt < 4; nt++)
#pragma unroll
            for (int i = 0; i < 4; i++) acc[mt][nt][i] = 0.f;

#define ISSUE(ic) do {                                                     \
        uint32_t st_ = sbase + ((ic) % NSTAGE) * STAGE_B;                  \
        int k0_ = (ic) * 32;                                               \
        cp_async16(st_ + s0,             gA0h + k0_);                      \
        cp_async16(st_ + s0 + BUF_B,     gA0l + k0_);                      \
        cp_async16(st_ + s0 + 2 * BUF_B, gB0h + k0_);                      \
        cp_async16(st_ + s0 + 3 * BUF_B, gB0l + k0_);                      \
        cp_async16(st_ + s1,             gA1h + k0_);                      \
        cp_async16(st_ + s1 + BUF_B,     gA1l + k0_);                      \
        cp_async16(st_ + s1 + 2 * BUF_B, gB1h + k0_);                      \
        cp_async16(st_ + s1 + 3 * BUF_B, gB1l + k0_);                      \
    } while (0)

    ISSUE(0); CP_COMMIT();
    ISSUE(1); CP_COMMIT();

    const uint32_t arow = (uint32_t)(wm * 64 + (lane & 15));
    const uint32_t asel = (arow >> 1) & 3;
    const uint32_t alc  = (uint32_t)(lane >> 4);
    const uint32_t aBase = arow * 64;
    const uint32_t brow = (uint32_t)(wn * 32 + (lane >> 4) * 8 + (lane & 7));
    const uint32_t bsel = (brow >> 1) & 3;
    const uint32_t blc  = (uint32_t)((lane >> 3) & 1);
    const uint32_t bBase = brow * 64;

    for (int ic = 0; ic < 32; ic++) {
        CP_WAIT1();
        __syncthreads();
        if (ic + 2 < 32) ISSUE(ic + 2);
        CP_COMMIT();

        const uint32_t st = sbase + (ic % NSTAGE) * STAGE_B;
#pragma unroll
        for (int ks = 0; ks < 2; ks++) {
            const uint32_t aoff = (((uint32_t)(ks * 2) + alc) ^ asel) << 4;
            const uint32_t boff = (((uint32_t)(ks * 2) + blc) ^ bsel) << 4;
            uint32_t ahi[4][4], alo[4][4];
#pragma unroll
            for (int mt = 0; mt < 4; mt++) {
                uint32_t off = st + aBase + mt * 1024 + aoff;
                ldsm_x4(ahi[mt][0], ahi[mt][1], ahi[mt][2], ahi[mt][3], off);
                ldsm_x4(alo[mt][0], alo[mt][1], alo[mt][2], alo[mt][3], off + BUF_B);
            }
            uint32_t bhi[4][2], blo[4][2];
#pragma unroll
            for (int np = 0; np < 2; np++) {
                uint32_t off = st + 2 * BUF_B + bBase + np * 1024 + boff;
                ldsm_x4(bhi[2 * np][0], bhi[2 * np][1], bhi[2 * np + 1][0], bhi[2 * np + 1][1], off);
                ldsm_x4(blo[2 * np][0], blo[2 * np][1], blo[2 * np + 1][0], blo[2 * np + 1][1],
                        off + BUF_B);
            }
#pragma unroll
            for (int mt = 0; mt < 4; mt++)
#pragma unroll
                for (int nt = 0; nt < 4; nt++) mma_bf16(acc[mt][nt], ahi[mt], bhi[nt]);
#pragma unroll
            for (int mt = 0; mt < 4; mt++)
#pragma unroll
                for (int nt = 0; nt < 4; nt++) mma_bf16(acc[mt][nt], ahi[mt], blo[nt]);
#pragma unroll
            for (int mt = 0; mt < 4; mt++)
#pragma unroll
                for (int nt = 0; nt < 4; nt++) mma_bf16(acc[mt][nt], alo[mt], bhi[nt]);
        }
    }
#undef ISSUE

    if (!EPI_T) {
        // row-major epilogue: bias + store out[l][d]
#pragma unroll
        for (int nt = 0; nt < 4; nt++) {
            int col = bn + wn * 32 + nt * 8 + (lane & 3) * 2;
            float bv0 = bias[col], bv1 = bias[col + 1];
#pragma unroll
            for (int mt = 0; mt < 4; mt++) {
                int row0 = bm + wm * 64 + mt * 16 + (lane >> 2);
                float2 o0, o1;
                o0.x = acc[mt][nt][0] + bv0; o0.y = acc[mt][nt][1] + bv1;
                o1.x = acc[mt][nt][2] + bv0; o1.y = acc[mt][nt][3] + bv1;
                *(float2*)(out + (size_t)row0 * DMODEL + col)       = o0;
                *(float2*)(out + (size_t)(row0 + 8) * DMODEL + col) = o1;
            }
        }
    } else {
        // transposing epilogue with bias, then: (a) coalesced g_ut write,
        // (b) fused scan phase-1 over this 128-step chunk -> g_e.
        float* sy = (float*)smem;                   // [l][d], stride 129 floats
        __syncthreads();                            // all LDSM of last chunk done
#pragma unroll
        for (int nt = 0; nt < 4; nt++) {
            int col = wn * 32 + nt * 8 + (lane & 3) * 2;
            float bv0 = bias[bn + col], bv1 = bias[bn + col + 1];
#pragma unroll
            for (int mt = 0; mt < 4; mt++) {
                int row0 = wm * 64 + mt * 16 + (lane >> 2);
                sy[row0 * 129 + col]           = acc[mt][nt][0] + bv0;
                sy[row0 * 129 + col + 1]       = acc[mt][nt][1] + bv1;
                sy[(row0 + 8) * 129 + col]     = acc[mt][nt][2] + bv0;
                sy[(row0 + 8) * 129 + col + 1] = acc[mt][nt][3] + bv1;
            }
        }
        __syncthreads();

        const int b    = bm >> 12;                  // batch (L_SEQ = 4096)
        const int lloc = bm & (L_SEQ - 1);          // l offset within batch
        // (a) write u to g_ut [b,D,L], coalesced along l
        {
            const int d    = tid >> 1;              // 0..127
            const int half = tid & 1;               // which 64 l's
            float* dst = out + ((size_t)b * DMODEL + bn + d) * L_SEQ + lloc + half * 64;
#pragma unroll
            for (int i = 0; i < 64; i += 4) {
                float4 v;
                v.x = sy[(half * 64 + i + 0) * 129 + d];
                v.y = sy[(half * 64 + i + 1) * 129 + d];
                v.z = sy[(half * 64 + i + 2) * 129 + d];
                v.w = sy[(half * 64 + i + 3) * 129 + d];
                *(float4*)(dst + i) = v;
            }
        }
        // (b) scan phase-1: 2 threads/channel x 32 states, 128 steps from smem
        {
            const int ch   = tid >> 1;              // local channel 0..127
            const int half = tid & 1;               // states [0,32) or [32,64)
            float dAv[32], h[32];
            const float* dAp = g_dA + (size_t)(bn + ch) * NSTATE + half * 32;
#pragma unroll
            for (int j = 0; j < 32; j += 4) {
                float4 v = *(const float4*)(dAp + j);
                dAv[j] = v.x; dAv[j + 1] = v.y; dAv[j + 2] = v.z; dAv[j + 3] = v.w;
                h[j] = 0.f; h[j + 1] = 0.f; h[j + 2] = 0.f; h[j + 3] = 0.f;
            }
            for (int l = 0; l < SCHUNK; l++) {
                float u = sy[l * 129 + ch];
#pragma unroll
                for (int j = 0; j < 32; j++) h[j] = fmaf(dAv[j], h[j], u);
            }
            const int chunk = lloc >> 7;            // SCHUNK = 128
            const int c = b * DMODEL + bn + ch;
            float* e = g_e + ((size_t)c * NCHUNK + chunk) * NSTATE + half * 32;
#pragma unroll
            for (int j = 0; j < 32; j += 4)
                *(float4*)(e + j) = make_float4(h[j], h[j + 1], h[j + 2], h[j + 3]);
        }
    }
}

// ---------------- carry combine: carry[ch] = dA^S*carry[ch-1] + e[ch-1] ----------
__global__ void __launch_bounds__(128) scan_carry() {
    const int lane = threadIdx.x & 31, wid = threadIdx.x >> 5;
    const int g = lane >> 3, sub = lane & 7;
    const int c = blockIdx.x * 16 + wid * 4 + g;
    const int d = c & (DMODEL - 1);

    float s[8], carry[8];
    float4 a0 = *(const float4*)&g_dA[d * NSTATE + sub * 8];
    float4 a1 = *(const float4*)&g_dA[d * NSTATE + sub * 8 + 4];
    s[0]=a0.x; s[1]=a0.y; s[2]=a0.z; s[3]=a0.w;
    s[4]=a1.x; s[5]=a1.y; s[6]=a1.z; s[7]=a1.w;
#pragma unroll
    for (int q = 0; q < 7; q++)            // dA^(2^7) = dA^SCHUNK (128)
#pragma unroll
        for (int j = 0; j < 8; j++) s[j] *= s[j];
#pragma unroll
    for (int j = 0; j < 8; j++) carry[j] = 0.f;

    for (int ch = 0; ch < NCHUNK; ch++) {
        float* cp = &g_carry[((size_t)c * NCHUNK + ch) * NSTATE + sub * 8];
        *(float4*)cp       = make_float4(carry[0], carry[1], carry[2], carry[3]);
        *(float4*)(cp + 4) = make_float4(carry[4], carry[5], carry[6], carry[7]);
        const float* e = &g_e[((size_t)c * NCHUNK + ch) * NSTATE + sub * 8];
        float4 e0 = *(const float4*)e;
        float4 e1 = *(const float4*)(e + 4);
        carry[0] = fmaf(s[0], carry[0], e0.x); carry[1] = fmaf(s[1], carry[1], e0.y);
        carry[2] = fmaf(s[2], carry[2], e0.z); carry[3] = fmaf(s[3], carry[3], e0.w);
        carry[4] = fmaf(s[4], carry[4], e1.x); carry[5] = fmaf(s[5], carry[5], e1.y);
        carry[6] = fmaf(s[6], carry[6], e1.z); carry[7] = fmaf(s[7], carry[7], e1.w);
    }
}

// ---------------- phase 3: outputs + fused transpose + bf16 split -> g_yh/g_yl
__global__ void __launch_bounds__(128) scan_out(const float* __restrict__ Dp) {
    __shared__ float sy[16 * 136];                  // [16 ch][128+8]
    const int tid = threadIdx.x;
    const int lane = tid & 31, wid = tid >> 5;
    const int g = lane >> 3, sub = lane & 7;
    const int ch16 = wid * 4 + g;                   // 0..15, block-local channel
    const int c = blockIdx.x * 16 + ch16;
    const int d = c & (DMODEL - 1);
    const int ch = blockIdx.y;

    const float* uc = g_ut + (size_t)c * L_SEQ + ch * SCHUNK;

    float dA[8], cb[8], h[8];
    float4 a0 = *(const float4*)&g_dA [d * NSTATE + sub * 8];
    float4 a1 = *(const float4*)&g_dA [d * NSTATE + sub * 8 + 4];
    float4 b0 = *(const float4*)&g_cdb[d * NSTATE + sub * 8];
    float4 b1 = *(const float4*)&g_cdb[d * NSTATE + sub * 8 + 4];
    dA[0]=a0.x; dA[1]=a0.y; dA[2]=a0.z; dA[3]=a0.w;
    dA[4]=a1.x; dA[5]=a1.y; dA[6]=a1.z; dA[7]=a1.w;
    cb[0]=b0.x; cb[1]=b0.y; cb[2]=b0.z; cb[3]=b0.w;
    cb[4]=b1.x; cb[5]=b1.y; cb[6]=b1.z; cb[7]=b1.w;
    const float* cp = &g_carry[((size_t)c * NCHUNK + ch) * NSTATE + sub * 8];
    float4 c0 = *(const float4*)cp;
    float4 c1 = *(const float4*)(cp + 4);
    h[0]=c0.x; h[1]=c0.y; h[2]=c0.z; h[3]=c0.w;
    h[4]=c1.x; h[5]=c1.y; h[6]=c1.z; h[7]=c1.w;
    const float dp = __ldg(&Dp[d]);

    for (int t0 = 0; t0 < SCHUNK; t0 += 8) {
        float4 ua = *(const float4*)(uc + t0);
        float4 ub = *(const float4*)(uc + t0 + 4);
        float uu[8] = {ua.x, ua.y, ua.z, ua.w, ub.x, ub.y, ub.z, ub.w};
        float yb[8];
#pragma unroll
        for (int s = 0; s < 8; s++) {
            float u = uu[s];
#pragma unroll
            for (int j = 0; j < 8; j++) h[j] = fmaf(dA[j], h[j], u);
            float p = 0.f;
#pragma unroll
            for (int j = 0; j < 8; j++) p = fmaf(cb[j], h[j], p);
            p += __shfl_xor_sync(0xffffffffu, p, 4);
            p += __shfl_xor_sync(0xffffffffu, p, 2);
            p += __shfl_xor_sync(0xffffffffu, p, 1);
            yb[s] = fmaf(dp, u, p);
        }
        float ov = yb[0];
#pragma unroll
        for (int s = 1; s < 8; s++) if (sub == s) ov = yb[s];
        sy[ch16 * 136 + t0 + sub] = ov;
    }
    __syncthreads();

    // write phase: transpose + split. rows = local t (128), cols = 16 channels.
    const int cbase = blockIdx.x * 16;          // global channel base
    const int b  = cbase >> 10;                 // DMODEL = 1024
    const int d0 = cbase & (DMODEL - 1);
    const int l0 = ch * SCHUNK;
    {
        const int r = tid;                      // 0..127
        uint32_t hiw[8], low[8];
#pragma unroll
        for (int q = 0; q < 8; q++) {
            float v0 = sy[(2 * q) * 136 + r];
            float v1 = sy[(2 * q + 1) * 136 + r];
            __nv_bfloat16 h0, l0b, h1, l1b;
            split2(v0, h0, l0b); split2(v1, h1, l1b);
            __nv_bfloat162 hp = __halves2bfloat162(h0, h1);
            __nv_bfloat162 lp = __halves2bfloat162(l0b, l1b);
            hiw[q] = *(uint32_t*)&hp; low[q] = *(uint32_t*)&lp;
        }
        size_t off = ((size_t)b * L_SEQ + l0 + r) * DMODEL + d0;
        *(uint4*)(g_yh + off)     = make_uint4(hiw[0], hiw[1], hiw[2], hiw[3]);
        *(uint4*)(g_yh + off + 8) = make_uint4(hiw[4], hiw[5], hiw[6], hiw[7]);
        *(uint4*)(g_yl + off)     = make_uint4(low[0], low[1], low[2], low[3]);
        *(uint4*)(g_yl + off + 8) = make_uint4(low[4], low[5], low[6], low[7]);
    }
}

// ---------------- launch ----------------
extern "C" void kernel_launch(void* const* d_in, const int* in_sizes, int n_in,
                              void* d_out, int out_size) {
    const float* x     = (const float*)d_in[0];
    const float* Win   = (const float*)d_in[1];
    const float* bin   = (const float*)d_in[2];
    const float* A_log = (const float*)d_in[3];
    const float* Bm    = (const float*)d_in[4];
    const float* Cm    = (const float*)d_in[5];
    const float* Dp    = (const float*)d_in[6];
    const float* dt    = (const float*)d_in[7];
    const float* Wout  = (const float*)d_in[8];
    const float* bout  = (const float*)d_in[9];
    float* out = (float*)d_out;

    static bool attr_set = false;
    if (!attr_set) {
        cudaFuncSetAttribute(gemm_hmma<true>,  cudaFuncAttributeMaxDynamicSharedMemorySize, GSMEM_B);
        cudaFuncSetAttribute(gemm_hmma<false>, cudaFuncAttributeMaxDynamicSharedMemorySize, GSMEM_B);
        attr_set = true;
    }

    __nv_bfloat16 *p_xh, *p_xl, *p_yh, *p_yl, *p_wih, *p_wil, *p_woh, *p_wol;
    cudaGetSymbolAddress((void**)&p_xh,  g_xh);
    cudaGetSymbolAddress((void**)&p_xl,  g_xl);
    cudaGetSymbolAddress((void**)&p_yh,  g_yh);
    cudaGetSymbolAddress((void**)&p_yl,  g_yl);
    cudaGetSymbolAddress((void**)&p_wih, g_winh);
    cudaGetSymbolAddress((void**)&p_wil, g_winl);
    cudaGetSymbolAddress((void**)&p_woh, g_wouth);
    cudaGetSymbolAddress((void**)&p_wol, g_woutl);
    float* p_ut;
    cudaGetSymbolAddress((void**)&p_ut, g_ut);

    // idx 0: merged prep + all bf16 splits
    prep_split<<<PREP_TOTAL / 256, 256>>>(x, Win, Wout, A_log, Bm, Cm, dt);

    // idx 1: in_proj GEMM + fused transpose (g_ut) + fused scan phase-1 (g_e)
    gemm_hmma<true><<<dim3(DMODEL / 128, M_ROWS / 128), 256, GSMEM_B>>>(
        p_xh, p_xl, p_wih, p_wil, bin, p_ut);

    // idx 2: carry combine
    scan_carry<<<(BATCH * DMODEL) / 16, 128>>>();

    // idx 3 (profiled slot): scan phase-3 + fused transpose/split
    scan_out<<<dim3((BATCH * DMODEL) / 16, NCHUNK), 128>>>(Dp);

    // idx 4: out_proj GEMM
    gemm_hmma<false><<<dim3(DMODEL / 128, M_ROWS / 128), 256, GSMEM_B>>>(
        p_yh, p_yl, p_woh, p_wol, bout, out);
}